// round 8
// baseline (speedup 1.0000x reference)
#include <cuda_runtime.h>

// 2D single-level DWT (L=2, Haar): pure 2x2 stencil per output group.
// Input : x[b][r][c], b<64, r,c<512 (f32). Output: quadrants [[ll,hl],[lh,hh]].
//
// R8: finest-grain mapping — ONE 2x2 input block per thread.
//   loads : 2x LDG.64 (__ldcs float2; warp reads 256B contiguous, nL=2)
//   stores: 4x STG.32 default policy (warp writes 128B contiguous per stream)
// Motivation: L1tex wavefront-queue model nw*n_LDG*nL = 49*2*2 = 196 < 248
// (no cross-CTA queue overflow), vs 392 for the float4-load mapping.
// Cache policy from R6 (best): input streamed (__ldcs), output default so it
// stays L2-resident and is rewritten in place across graph replays.

__global__ void __launch_bounds__(256) dwt_haar_kernel(
    const float* __restrict__ x,
    const float* __restrict__ lpf,
    const float* __restrict__ hpf,
    float* __restrict__ out)
{
    // t in [0,256): output col within subband; n in [0,256): subband row; b: batch
    const int gid = blockIdx.x * blockDim.x + threadIdx.x;
    const int t = gid & 255;
    const int n = (gid >> 8) & 255;
    const int b = gid >> 16;

    const long long img = (long long)b * (512 * 512);
    const float* p0 = x + img + (long long)(2 * n) * 512 + 2 * t;

    const float2 r0 = __ldcs(reinterpret_cast<const float2*>(p0));
    const float2 r1 = __ldcs(reinterpret_cast<const float2*>(p0 + 512));

    const float lo0 = __ldg(&lpf[0]);
    const float lo1 = __ldg(&lpf[1]);
    const float hi0 = __ldg(&hpf[0]);
    const float hi1 = __ldg(&hpf[1]);

    const float at = lo0 * r0.x + lo1 * r0.y;
    const float ab = lo0 * r1.x + lo1 * r1.y;
    const float dt = hi0 * r0.x + hi1 * r0.y;
    const float db = hi0 * r1.x + hi1 * r1.y;

    const float ll = lo0 * at + lo1 * ab;
    const float lh = hi0 * at + hi1 * ab;
    const float hl = lo0 * dt + lo1 * db;
    const float hh = hi0 * dt + hi1 * db;

    float* o_ll = out + img + (long long)n * 512 + t;
    float* o_lh = out + img + (long long)(n + 256) * 512 + t;

    o_ll[0]   = ll;
    o_ll[256] = hl;
    o_lh[0]   = lh;
    o_lh[256] = hh;
}

extern "C" void kernel_launch(void* const* d_in, const int* in_sizes, int n_in,
                              void* d_out, int out_size)
{
    const float* x   = (const float*)d_in[0];
    const float* lpf = (const float*)d_in[1];
    const float* hpf = (const float*)d_in[2];
    float* out = (float*)d_out;

    const int total = 64 * 256 * 256;  // 4,194,304 threads
    dwt_haar_kernel<<<total / 256, 256>>>(x, lpf, hpf, out);
}

// round 9
// speedup vs baseline: 1.1099x; 1.1099x over previous
#include <cuda_runtime.h>

// 2D single-level DWT (L=2, Haar): pure 2x2 stencil per output group.
// Input : x[b][r][c], b<64, r,c<512 (f32). Output: quadrants [[ll,hl],[lh,hh]].
//
// Best configuration (R6) + micro-tune:
//  - mapping: thread = 2 adjacent 2x2 blocks (2x LDG.128 in, 4x STG.64 out)
//  - policy : input __ldcs (evict-first: never displaces resident output),
//             output default (stays dirty in L2, rewritten in place per replay)
//  - R9     : filters loaded as 2x float2 (was 4 scalar LDG), 512-thread blocks.

__global__ void __launch_bounds__(512) dwt_haar_kernel(
    const float* __restrict__ x,
    const float* __restrict__ lpf,
    const float* __restrict__ hpf,
    float* __restrict__ out)
{
    // t in [0,128): width-pair index, n in [0,256): subband row, b: batch
    const int gid = blockIdx.x * blockDim.x + threadIdx.x;
    const int t = gid & 127;
    const int n = (gid >> 7) & 255;
    const int b = gid >> 15;

    const long long img = (long long)b * (512 * 512);
    const float* p0 = x + img + (long long)(2 * n) * 512 + 4 * t;

    // Streaming loads: evict-first so the input never displaces the output.
    const float4 r0 = __ldcs(reinterpret_cast<const float4*>(p0));
    const float4 r1 = __ldcs(reinterpret_cast<const float4*>(p0 + 512));

    const float2 lo = __ldg(reinterpret_cast<const float2*>(lpf));
    const float2 hi = __ldg(reinterpret_cast<const float2*>(hpf));
    const float lo0 = lo.x, lo1 = lo.y;
    const float hi0 = hi.x, hi1 = hi.y;

    float2 ll, lh, hl, hh;
    {
        float at = lo0 * r0.x + lo1 * r0.y, ab = lo0 * r1.x + lo1 * r1.y;
        float dt = hi0 * r0.x + hi1 * r0.y, db = hi0 * r1.x + hi1 * r1.y;
        ll.x = lo0 * at + lo1 * ab;  lh.x = hi0 * at + hi1 * ab;
        hl.x = lo0 * dt + lo1 * db;  hh.x = hi0 * dt + hi1 * db;
    }
    {
        float at = lo0 * r0.z + lo1 * r0.w, ab = lo0 * r1.z + lo1 * r1.w;
        float dt = hi0 * r0.z + hi1 * r0.w, db = hi0 * r1.z + hi1 * r1.w;
        ll.y = lo0 * at + lo1 * ab;  lh.y = hi0 * at + hi1 * ab;
        hl.y = lo0 * dt + lo1 * db;  hh.y = hi0 * dt + hi1 * db;
    }

    const int m = 2 * t;
    float* o_ll = out + img + (long long)n * 512 + m;
    float* o_lh = out + img + (long long)(n + 256) * 512 + m;

    // Default stores: output stays L2-resident, rewritten in place per replay.
    *reinterpret_cast<float2*>(o_ll)       = ll;
    *reinterpret_cast<float2*>(o_ll + 256) = hl;
    *reinterpret_cast<float2*>(o_lh)       = lh;
    *reinterpret_cast<float2*>(o_lh + 256) = hh;
}

extern "C" void kernel_launch(void* const* d_in, const int* in_sizes, int n_in,
                              void* d_out, int out_size)
{
    const float* x   = (const float*)d_in[0];
    const float* lpf = (const float*)d_in[1];
    const float* hpf = (const float*)d_in[2];
    float* out = (float*)d_out;

    const int total = 64 * 256 * 128;  // 2,097,152 threads
    dwt_haar_kernel<<<total / 512, 512>>>(x, lpf, hpf, out);
}